// round 2
// baseline (speedup 1.0000x reference)
#include <cuda_runtime.h>
#include <cstdint>

// Problem constants
#define M_ROWS (16 * 8192)   // B*N = 131072
#define DDIM 128
#define CDIM 64
#define INV_TEMP (1.0f / 6.0f)   // temp = 2*(1+192/96) = 6

// Pass-1 tiling
#define BR 128               // rows per block
#define XS_STRIDE 132        // x tile row stride (floats), 128 + 4 pad
#define DT_STRIDE 68         // dictT row stride (floats), 64 + 4 pad
#define SC_STRIDE 68         // scores row stride

#define SMEM_FLOATS (128 * DT_STRIDE + BR * XS_STRIDE + BR * SC_STRIDE)
#define SMEM_BYTES (SMEM_FLOATS * 4)

// -------------------- scratch (device globals; no allocs) --------------------
__device__ __align__(16) float g_q[(size_t)M_ROWS * CDIM];  // soft assignments
__device__ float g_f[CDIM];                                  // column sums of q
__device__ float g_kl;                                       // KL accumulator

// -------------------- packed f32x2 helpers --------------------
__device__ __forceinline__ unsigned long long pack_dup(float x) {
    unsigned long long r;
    unsigned int xu = __float_as_uint(x);
    asm("mov.b64 %0, {%1, %1};" : "=l"(r) : "r"(xu));
    return r;
}
__device__ __forceinline__ void fma2(unsigned long long& acc,
                                     unsigned long long a,
                                     unsigned long long b) {
    asm("fma.rn.f32x2 %0, %1, %2, %0;" : "+l"(acc) : "l"(a), "l"(b));
}
__device__ __forceinline__ void unpack2(unsigned long long v, float& lo, float& hi) {
    unsigned int l, h;
    asm("mov.b64 {%0, %1}, %2;" : "=r"(l), "=r"(h) : "l"(v));
    lo = __uint_as_float(l);
    hi = __uint_as_float(h);
}

// -------------------- kernel 0: zero accumulators --------------------
__global__ void zero_kernel() {
    int t = threadIdx.x;
    if (t < CDIM) g_f[t] = 0.0f;
    if (t == CDIM) g_kl = 0.0f;
}

// -------------------- kernel 1: GEMM + softmax + topk + outputs --------------------
__global__ __launch_bounds__(256, 1) void pass1_kernel(
    const float* __restrict__ x,
    const float* __restrict__ dict,
    float* __restrict__ out_common,
    float* __restrict__ out_res) {
    extern __shared__ float sm[];
    float* dictT = sm;                           // [128][DT_STRIDE]: dictT[d][c]
    float* x_s = sm + 128 * DT_STRIDE;           // [BR][XS_STRIDE]
    float* sc = x_s + BR * XS_STRIDE;            // [BR][SC_STRIDE] scores -> q

    const int tid = threadIdx.x;
    const int row0 = blockIdx.x * BR;

    // --- load dict transposed: warp writes 32 distinct c at same d -> bank-clean
    {
        const int c = tid & 63;
        const int base = tid >> 6;  // 0..3
        const float4* dsrc = reinterpret_cast<const float4*>(dict);
#pragma unroll
        for (int j = 0; j < 8; ++j) {
            int dch = base + 4 * j;           // 0..31
            float4 v = dsrc[c * 32 + dch];    // dict[c][4*dch .. +3]
            int d0 = dch * 4;
            dictT[(d0 + 0) * DT_STRIDE + c] = v.x;
            dictT[(d0 + 1) * DT_STRIDE + c] = v.y;
            dictT[(d0 + 2) * DT_STRIDE + c] = v.z;
            dictT[(d0 + 3) * DT_STRIDE + c] = v.w;
        }
    }
    // --- load x tile (coalesced float4)
    {
        const float4* xsrc = reinterpret_cast<const float4*>(x + (size_t)row0 * DDIM);
#pragma unroll
        for (int j = 0; j < 16; ++j) {
            int idx4 = tid + 256 * j;  // 0..4095
            float4 v = xsrc[idx4];
            int r = idx4 >> 5;
            int d0 = (idx4 & 31) * 4;
            *reinterpret_cast<float4*>(&x_s[r * XS_STRIDE + d0]) = v;
        }
    }
    __syncthreads();

    // --- GEMM: per thread 4 rows x 8 cols (4 f32x2 col-pairs)
    {
        const int rg = tid >> 3;   // 0..31
        const int cg = tid & 7;    // 0..7
        const int r0 = rg * 4;
        unsigned long long acc[4][4];
#pragma unroll
        for (int i = 0; i < 4; ++i)
#pragma unroll
            for (int p = 0; p < 4; ++p) acc[i][p] = 0ull;

        const ulonglong2* dptr =
            reinterpret_cast<const ulonglong2*>(dictT) + cg * 2;  // 17 u64x2 per d-row
#pragma unroll 8
        for (int k = 0; k < DDIM; ++k) {
            unsigned long long xp0 = pack_dup(x_s[(r0 + 0) * XS_STRIDE + k]);
            unsigned long long xp1 = pack_dup(x_s[(r0 + 1) * XS_STRIDE + k]);
            unsigned long long xp2 = pack_dup(x_s[(r0 + 2) * XS_STRIDE + k]);
            unsigned long long xp3 = pack_dup(x_s[(r0 + 3) * XS_STRIDE + k]);
            ulonglong2 dA = dptr[k * 17];
            ulonglong2 dB = dptr[k * 17 + 1];
            fma2(acc[0][0], xp0, dA.x); fma2(acc[0][1], xp0, dA.y);
            fma2(acc[0][2], xp0, dB.x); fma2(acc[0][3], xp0, dB.y);
            fma2(acc[1][0], xp1, dA.x); fma2(acc[1][1], xp1, dA.y);
            fma2(acc[1][2], xp1, dB.x); fma2(acc[1][3], xp1, dB.y);
            fma2(acc[2][0], xp2, dA.x); fma2(acc[2][1], xp2, dA.y);
            fma2(acc[2][2], xp2, dB.x); fma2(acc[2][3], xp2, dB.y);
            fma2(acc[3][0], xp3, dA.x); fma2(acc[3][1], xp3, dA.y);
            fma2(acc[3][2], xp3, dB.x); fma2(acc[3][3], xp3, dB.y);
        }
        // store scores to smem
#pragma unroll
        for (int i = 0; i < 4; ++i) {
            float* dst = &sc[(r0 + i) * SC_STRIDE + cg * 8];
            float4 v0, v1;
            unpack2(acc[i][0], v0.x, v0.y);
            unpack2(acc[i][1], v0.z, v0.w);
            unpack2(acc[i][2], v1.x, v1.y);
            unpack2(acc[i][3], v1.z, v1.w);
            *reinterpret_cast<float4*>(dst) = v0;
            *reinterpret_cast<float4*>(dst + 4) = v1;
        }
    }
    __syncthreads();

    // --- row phase: pair of threads (lane^1) per row, each handles 32 cols
    {
        const int r = tid >> 1;
        const int h = tid & 1;
        const int rowg = row0 + r;
        float* srow = &sc[r * SC_STRIDE + h * 32];

        float s[32];
#pragma unroll
        for (int j = 0; j < 8; ++j) {
            float4 v = *reinterpret_cast<float4*>(srow + 4 * j);
            s[4 * j + 0] = v.x; s[4 * j + 1] = v.y;
            s[4 * j + 2] = v.z; s[4 * j + 3] = v.w;
        }

        // row max (pairwise)
        float m = s[0];
#pragma unroll
        for (int j = 1; j < 32; ++j) m = fmaxf(m, s[j]);
        m = fmaxf(m, __shfl_xor_sync(0xFFFFFFFFu, m, 1));

        // local top-4
        float tv0 = -1e30f, tv1 = -1e30f, tv2 = -1e30f, tv3 = -1e30f;
        int ti0 = 0, ti1 = 0, ti2 = 0, ti3 = 0;
#pragma unroll
        for (int j = 0; j < 32; ++j) {
            float v = s[j];
            int c = h * 32 + j;
            if (v > tv3) {
                if (v > tv1) {
                    if (v > tv0) {
                        tv3 = tv2; ti3 = ti2; tv2 = tv1; ti2 = ti1;
                        tv1 = tv0; ti1 = ti0; tv0 = v; ti0 = c;
                    } else {
                        tv3 = tv2; ti3 = ti2; tv2 = tv1; ti2 = ti1;
                        tv1 = v; ti1 = c;
                    }
                } else {
                    if (v > tv2) {
                        tv3 = tv2; ti3 = ti2; tv2 = v; ti2 = c;
                    } else {
                        tv3 = v; ti3 = c;
                    }
                }
            }
        }

        // exp + sum (overwrite s with e)
        float S = 0.0f;
#pragma unroll
        for (int j = 0; j < 32; ++j) {
            float e = __expf((s[j] - m) * INV_TEMP);
            s[j] = e;
            S += e;
        }
        S += __shfl_xor_sync(0xFFFFFFFFu, S, 1);
        float invS = 1.0f / S;

        // write q to global scratch + back to smem (for column sums)
        float* qg = &g_q[(size_t)rowg * CDIM + h * 32];
#pragma unroll
        for (int j = 0; j < 8; ++j) {
            float4 v;
            v.x = s[4 * j + 0] * invS; v.y = s[4 * j + 1] * invS;
            v.z = s[4 * j + 2] * invS; v.w = s[4 * j + 3] * invS;
            *reinterpret_cast<float4*>(qg + 4 * j) = v;
            *reinterpret_cast<float4*>(srow + 4 * j) = v;
        }

        // merge top-4 with partner (A = low-col half -> stable tie to lower idx)
        float pv[4]; int pi[4];
        float tvv[4] = {tv0, tv1, tv2, tv3};
        int tii[4] = {ti0, ti1, ti2, ti3};
#pragma unroll
        for (int k2 = 0; k2 < 4; ++k2) {
            pv[k2] = __shfl_xor_sync(0xFFFFFFFFu, tvv[k2], 1);
            pi[k2] = __shfl_xor_sync(0xFFFFFFFFu, tii[k2], 1);
        }
        float Av[4], Bv[4]; int Ai[4], Bi[4];
#pragma unroll
        for (int k2 = 0; k2 < 4; ++k2) {
            Av[k2] = (h == 0) ? tvv[k2] : pv[k2];
            Ai[k2] = (h == 0) ? tii[k2] : pi[k2];
            Bv[k2] = (h == 0) ? pv[k2] : tvv[k2];
            Bi[k2] = (h == 0) ? pi[k2] : tii[k2];
        }
        float mv[4]; int mi[4];
        {
            int a = 0, b = 0;
#pragma unroll
            for (int k2 = 0; k2 < 4; ++k2) {
                bool ta = (Av[a] >= Bv[b]);
                mv[k2] = ta ? Av[a] : Bv[b];
                mi[k2] = ta ? Ai[a] : Bi[b];
                a += ta ? 1 : 0;
                b += ta ? 0 : 1;
            }
        }

        // softmax weights over top-4 (mv[0] is max)
        float e1 = __expf((mv[1] - mv[0]) * INV_TEMP);
        float e2 = __expf((mv[2] - mv[0]) * INV_TEMP);
        float e3 = __expf((mv[3] - mv[0]) * INV_TEMP);
        float wn = 1.0f / (1.0f + e1 + e2 + e3);
        float w0 = wn, w1 = e1 * wn, w2 = e2 * wn, w3 = e3 * wn;
        int i0 = mi[0], i1 = mi[1], i2 = mi[2], i3 = mi[3];

        // x_common / x_residual for this half's 64 dims
        const float* xr = &x_s[r * XS_STRIDE];
        float* oc = out_common + (size_t)rowg * DDIM;
        float* orr = out_res + (size_t)rowg * DDIM;
        const int dbase = h * 64;
#pragma unroll
        for (int dd = 0; dd < 64; dd += 4) {
            int d0 = dbase + dd;
            float4 xv = *reinterpret_cast<const float4*>(xr + d0);
            float4 cm;
            cm.x = w0 * dictT[(d0 + 0) * DT_STRIDE + i0] + w1 * dictT[(d0 + 0) * DT_STRIDE + i1] +
                   w2 * dictT[(d0 + 0) * DT_STRIDE + i2] + w3 * dictT[(d0 + 0) * DT_STRIDE + i3];
            cm.y = w0 * dictT[(d0 + 1) * DT_STRIDE + i0] + w1 * dictT[(d0 + 1) * DT_STRIDE + i1] +
                   w2 * dictT[(d0 + 1) * DT_STRIDE + i2] + w3 * dictT[(d0 + 1) * DT_STRIDE + i3];
            cm.z = w0 * dictT[(d0 + 2) * DT_STRIDE + i0] + w1 * dictT[(d0 + 2) * DT_STRIDE + i1] +
                   w2 * dictT[(d0 + 2) * DT_STRIDE + i2] + w3 * dictT[(d0 + 2) * DT_STRIDE + i3];
            cm.w = w0 * dictT[(d0 + 3) * DT_STRIDE + i0] + w1 * dictT[(d0 + 3) * DT_STRIDE + i1] +
                   w2 * dictT[(d0 + 3) * DT_STRIDE + i2] + w3 * dictT[(d0 + 3) * DT_STRIDE + i3];
            *reinterpret_cast<float4*>(oc + d0) = cm;
            float4 rs;
            rs.x = xv.x - cm.x; rs.y = xv.y - cm.y;
            rs.z = xv.z - cm.z; rs.w = xv.w - cm.w;
            *reinterpret_cast<float4*>(orr + d0) = rs;
        }
    }
    __syncthreads();

    // --- block column sums of q -> global atomics (64 per block)
    if (tid < CDIM) {
        float sum = 0.0f;
#pragma unroll 4
        for (int rr = 0; rr < BR; ++rr) sum += sc[rr * SC_STRIDE + tid];
        atomicAdd(&g_f[tid], sum);
    }
}

// -------------------- kernel 2: KL from stored q --------------------
__global__ __launch_bounds__(256) void pass2_kernel() {
    __shared__ float invf_s[CDIM], logf_s[CDIM];
    __shared__ float wsum[8];
    int tid = threadIdx.x;
    if (tid < CDIM) {
        float f = g_f[tid];
        invf_s[tid] = 1.0f / f;
        logf_s[tid] = __logf(f);
    }
    __syncthreads();

    int row = blockIdx.x * 256 + tid;
    const float* q = &g_q[(size_t)row * CDIM];
    float A = 0.0f, W = 0.0f;
#pragma unroll
    for (int c0 = 0; c0 < CDIM; c0 += 4) {
        float4 v = *reinterpret_cast<const float4*>(q + c0);
        float qv[4] = {v.x, v.y, v.z, v.w};
#pragma unroll
        for (int i = 0; i < 4; ++i) {
            int c = c0 + i;
            float qq = qv[i] * qv[i] * invf_s[c];
            W += qq;
            A += qq * (__logf(qv[i]) - logf_s[c]);
        }
    }
    float term = A / W - __logf(W);

#pragma unroll
    for (int o = 16; o; o >>= 1) term += __shfl_xor_sync(0xFFFFFFFFu, term, o);
    if ((tid & 31) == 0) wsum[tid >> 5] = term;
    __syncthreads();
    if (tid == 0) {
        float t = 0.0f;
#pragma unroll
        for (int i = 0; i < 8; ++i) t += wsum[i];
        atomicAdd(&g_kl, t);
    }
}

// -------------------- kernel 3: ortho loss + finalize aux --------------------
__global__ __launch_bounds__(256) void pass3_kernel(const float* __restrict__ dict,
                                                    float* __restrict__ out_aux) {
    __shared__ float ds[CDIM * DDIM];  // 32 KB
    __shared__ float ws[8];
    int tid = threadIdx.x;
    for (int i = tid; i < CDIM * DDIM / 4; i += 256)
        reinterpret_cast<float4*>(ds)[i] = reinterpret_cast<const float4*>(dict)[i];
    __syncthreads();

    float acc = 0.0f;
    for (int p = tid; p < CDIM * CDIM; p += 256) {
        int i = p >> 6, j = p & 63;
        const float* a = &ds[i * DDIM];
        const float* b = &ds[j * DDIM];
        float dot = 0.0f;
#pragma unroll 8
        for (int d = 0; d < DDIM; ++d) dot += a[d] * b[d];
        float diff = dot - ((i == j) ? 1.0f : 0.0f);
        acc += diff * diff;
    }
#pragma unroll
    for (int o = 16; o; o >>= 1) acc += __shfl_xor_sync(0xFFFFFFFFu, acc, o);
    if ((tid & 31) == 0) ws[tid >> 5] = acc;
    __syncthreads();
    if (tid == 0) {
        float t = 0.0f;
#pragma unroll
        for (int i = 0; i < 8; ++i) t += ws[i];
        float ortho = t / (float)(CDIM * CDIM);
        float kl = g_kl / (float)M_ROWS;
        out_aux[0] = 0.5f * kl + 0.1f * ortho;  // SEQ/PRED = 0.5
    }
}

// -------------------- launch --------------------
extern "C" void kernel_launch(void* const* d_in, const int* in_sizes, int n_in,
                              void* d_out, int out_size) {
    const float* x = (const float*)d_in[0];      // (B, N, D) fp32
    const float* dict = (const float*)d_in[1];   // (C, D) fp32
    float* out = (float*)d_out;
    float* out_common = out;
    float* out_res = out + (size_t)M_ROWS * DDIM;
    float* out_aux = out + (size_t)2 * M_ROWS * DDIM;

    cudaFuncSetAttribute(pass1_kernel, cudaFuncAttributeMaxDynamicSharedMemorySize,
                         SMEM_BYTES);

    zero_kernel<<<1, 128>>>();
    pass1_kernel<<<M_ROWS / BR, 256, SMEM_BYTES>>>(x, dict, out_common, out_res);
    pass2_kernel<<<M_ROWS / 256, 256>>>();
    pass3_kernel<<<1, 256>>>(dict, out_aux);
}